// round 4
// baseline (speedup 1.0000x reference)
#include <cuda_runtime.h>

// diff[K, N, D] = x[None, :, :] - centroid[:, None, :]
// N=65536, K=32, D=64, fp32. Store-roofline: 536 MB out.
// R3 confirmed: DRAM write efficiency improves as concurrent write streams
// shrink (row-buffer locality). Push KG 4 -> 2 (gridDim.y = 16).
// x re-read 16x but L2-resident (16 MB << 126 MB); L2 read headroom exists.

#define N_PTS 65536
#define K_CENT 32
#define D_DIM 64
#define D4 (D_DIM / 4)            // 16 float4 per row
#define KG 2                      // k's per CTA
#define KY (K_CENT / KG)          // gridDim.y = 16
#define CENT_F4 (KG * D4)         // 32 float4 = 512 B staged per CTA
#define THREADS 256

__global__ void __launch_bounds__(THREADS, 8)
kmeans_diff_kernel(const float4* __restrict__ x,
                   const float4* __restrict__ cent,
                   float4* __restrict__ out) {
    __shared__ float4 sc[CENT_F4];

    const int k0 = blockIdx.y * KG;

    // Stage this CTA's KG centroid rows into shared.
    for (int i = threadIdx.x; i < CENT_F4; i += blockDim.x)
        sc[i] = cent[k0 * D4 + i];
    __syncthreads();

    const unsigned idx = blockIdx.x * THREADS + threadIdx.x;  // [0, N*D/4)
    const unsigned d4 = idx & (D4 - 1);

    const float4 xv = x[idx];  // DRAM first wave, L2 hit afterwards

    const size_t plane = (size_t)N_PTS * D4;  // float4 per k-plane
    float4* o = out + (size_t)k0 * plane + idx;

#pragma unroll
    for (int kk = 0; kk < KG; kk++) {
        const float4 c = sc[kk * D4 + d4];
        float4 r;
        r.x = xv.x - c.x;
        r.y = xv.y - c.y;
        r.z = xv.z - c.z;
        r.w = xv.w - c.w;
        __stcs(o, r);            // streaming: write-once, keep x in L2
        o += plane;
    }
}

extern "C" void kernel_launch(void* const* d_in, const int* in_sizes, int n_in,
                              void* d_out, int out_size) {
    const float4* x    = (const float4*)d_in[0];   // [N, D] fp32
    const float4* cent = (const float4*)d_in[1];   // [K, D] fp32
    float4* out        = (float4*)d_out;           // [K, N, D] fp32

    const int total_f4 = N_PTS * D4;               // 1,048,576
    dim3 grid(total_f4 / THREADS, KY);             // (4096, 16)
    kmeans_diff_kernel<<<grid, THREADS>>>(x, cent, out);
}